// round 6
// baseline (speedup 1.0000x reference)
#include <cuda_runtime.h>
#include <cuda_bf16.h>
#include <math.h>
#include <stdint.h>

#define NNODES 20000
#define NGROUP 400
#define MAXG   512

// ---------------- scratch (static device allocations; no cudaMalloc) ----------
__device__ float g_bufA[NNODES * 256];
__device__ float g_bufB[NNODES * 256];
__device__ __nv_bfloat16 g_actH[NNODES * 256];
__device__ __nv_bfloat16 g_actL[NNODES * 256];
__device__ int   g_members[NGROUP * MAXG];
__device__ int   g_cnt[NGROUP];
__device__ float g_dis[NNODES];
__device__ int   g_is64;

// bf16 hi/lo transposed weights: [N][K] row-major
__device__ __nv_bfloat16 g_w1h[256 * 128], g_w1l[256 * 128];
__device__ __nv_bfloat16 g_w2h[256 * 256], g_w2l[256 * 256];
__device__ __nv_bfloat16 g_w3h[128 * 256], g_w3l[128 * 256];

__device__ __forceinline__ uint32_t pack_bf16x2(float a, float b) {
    __nv_bfloat162 t = __floats2bfloat162_rn(a, b);
    return *reinterpret_cast<uint32_t*>(&t);
}

// ---------------- 0) dtype detection for idx ---------------------------------
__global__ void detect_dtype(const int* __restrict__ idx32, int n) {
    int i = threadIdx.x;
    bool bad = false;
    if (i < n / 2) {
        int lo = idx32[2 * i];
        int hi = idx32[2 * i + 1];
        bad = (hi != 0) || (lo < 0) || (lo >= NGROUP);
    }
    unsigned m = __ballot_sync(0xffffffffu, bad);
    __shared__ unsigned s_any[8];
    if ((threadIdx.x & 31) == 0) s_any[threadIdx.x >> 5] = m;
    __syncthreads();
    if (threadIdx.x == 0) {
        unsigned any = 0;
#pragma unroll
        for (int w = 0; w < 8; w++) any |= s_any[w];
        g_is64 = (any == 0) ? 1 : 0;
    }
}

// ---------------- 1) group build (4 elems/thread/tile) ------------------------
__global__ __launch_bounds__(256) void build_groups(const void* __restrict__ idx_raw, int n) {
    const int g    = blockIdx.x;
    const int tid  = threadIdx.x;
    const int lane = tid & 31;
    const int warp = tid >> 5;
    const int is64 = g_is64;
    const int*       idx32 = (const int*)idx_raw;
    const long long* idx64 = (const long long*)idx_raw;

    __shared__ int warp_sums[8];
    __shared__ int s_base;
    if (tid == 0) s_base = 0;
    __syncthreads();

    for (int t0 = 0; t0 < n; t0 += 1024) {
        int i0 = t0 + tid * 4;
        int v[4];
        if (!is64 && i0 + 3 < n) {
            int4 q = *reinterpret_cast<const int4*>(&idx32[i0]);
            v[0] = q.x; v[1] = q.y; v[2] = q.z; v[3] = q.w;
        } else {
#pragma unroll
            for (int j = 0; j < 4; j++) {
                int i = i0 + j;
                v[j] = (i < n) ? (is64 ? (int)idx64[i] : idx32[i]) : -1;
            }
        }
        unsigned m[4];
#pragma unroll
        for (int j = 0; j < 4; j++) m[j] = __ballot_sync(0xffffffffu, v[j] == g);
        unsigned lt = (1u << lane) - 1u;
        int lanebase = 0, wtotal = 0;
#pragma unroll
        for (int j = 0; j < 4; j++) { lanebase += __popc(m[j] & lt); wtotal += __popc(m[j]); }
        if (lane == 0) warp_sums[warp] = wtotal;
        __syncthreads();
        int woff = 0, tile_total = 0;
#pragma unroll
        for (int w = 0; w < 8; w++) {
            if (w < warp) woff += warp_sums[w];
            tile_total += warp_sums[w];
        }
        int mycnt = 0;
#pragma unroll
        for (int j = 0; j < 4; j++) {
            if (v[j] == g) {
                int pos = s_base + woff + lanebase + mycnt;
                g_members[g * MAXG + pos] = i0 + j;
                g_dis[i0 + j] = rsqrtf((float)(pos + 1));
                mycnt++;
            }
        }
        __syncthreads();
        if (tid == 0) s_base += tile_total;
        __syncthreads();
    }
    if (tid == 0) g_cnt[g] = s_base;
}

// ---------------- 2a) weight prep: tiled transpose + bf16 hi/lo split ---------
__global__ __launch_bounds__(256) void prep_w_t(const float* __restrict__ W,
                                                __nv_bfloat16* __restrict__ oh,
                                                __nv_bfloat16* __restrict__ ol, int K, int N) {
    __shared__ __nv_bfloat16 shh[32][33], shl[32][33];
    const int k0 = blockIdx.x * 32, n0 = blockIdx.y * 32;
    const int tx = threadIdx.x, ty = threadIdx.y;
#pragma unroll
    for (int j = 0; j < 4; j++) {
        int kk = ty + j * 8;
        float v = W[(size_t)(k0 + kk) * N + n0 + tx];
        __nv_bfloat16 h = __float2bfloat16(v);
        shh[kk][tx] = h;
        shl[kk][tx] = __float2bfloat16(v - __bfloat162float(h));
    }
    __syncthreads();
#pragma unroll
    for (int j = 0; j < 4; j++) {
        int nn = ty + j * 8;
        oh[(size_t)(n0 + nn) * K + k0 + tx] = shh[tx][nn];
        ol[(size_t)(n0 + nn) * K + k0 + tx] = shl[tx][nn];
    }
}

// ---------------- 2b) activation fp32 -> bf16 hi/lo ---------------------------
__global__ void conv_split(const float* __restrict__ A, __nv_bfloat16* __restrict__ oh,
                           __nv_bfloat16* __restrict__ ol, int total4) {
    int e = blockIdx.x * 256 + threadIdx.x;
    if (e >= total4) return;
    float4 a = *reinterpret_cast<const float4*>(&A[(size_t)e * 4]);
    __nv_bfloat16 h0 = __float2bfloat16(a.x), h1 = __float2bfloat16(a.y);
    __nv_bfloat16 h2 = __float2bfloat16(a.z), h3 = __float2bfloat16(a.w);
    uint2 uh, ul;
    uh.x = ((uint32_t)*(uint16_t*)&h1 << 16) | *(uint16_t*)&h0;
    uh.y = ((uint32_t)*(uint16_t*)&h3 << 16) | *(uint16_t*)&h2;
    ul.x = pack_bf16x2(a.x - __bfloat162float(h0), a.y - __bfloat162float(h1));
    ul.y = pack_bf16x2(a.z - __bfloat162float(h2), a.w - __bfloat162float(h3));
    *reinterpret_cast<uint2*>(&oh[(size_t)e * 4]) = uh;
    *reinterpret_cast<uint2*>(&ol[(size_t)e * 4]) = ul;
}

// ---------------- 3) HMMA GEMM (R4 geometry, bf16 A) --------------------------
// C[M,N] = A @ W^T. A bf16 hi/lo [M][K]; W bf16 hi/lo [N][K].
// BM=128, BN=128, BK=32, 256 threads: warps 2(M)x4(N), warp tile 64x32.
#define LDMX4(r0, r1, r2, r3, addr) \
    asm volatile("ldmatrix.sync.aligned.m8n8.x4.shared.b16 {%0,%1,%2,%3}, [%4];" \
                 : "=r"(r0), "=r"(r1), "=r"(r2), "=r"(r3) : "r"(addr))
#define MMA16816(c, a, b) \
    asm volatile("mma.sync.aligned.m16n8k16.row.col.f32.bf16.bf16.f32 " \
                 "{%0,%1,%2,%3}, {%4,%5,%6,%7}, {%8,%9}, {%0,%1,%2,%3};" \
                 : "+f"((c)[0]), "+f"((c)[1]), "+f"((c)[2]), "+f"((c)[3]) \
                 : "r"((a)[0]), "r"((a)[1]), "r"((a)[2]), "r"((a)[3]), \
                   "r"((b)[0]), "r"((b)[1]))

__global__ __launch_bounds__(256) void gemm_mma(const __nv_bfloat16* __restrict__ Ah,
                                                const __nv_bfloat16* __restrict__ Al,
                                                const __nv_bfloat16* __restrict__ Wh,
                                                const __nv_bfloat16* __restrict__ Wl,
                                                float* __restrict__ C,
                                                int M, int K, int N) {
    __shared__ __nv_bfloat16 sAh[128][40];
    __shared__ __nv_bfloat16 sAl[128][40];
    __shared__ __nv_bfloat16 sBh[128][40];
    __shared__ __nv_bfloat16 sBl[128][40];

    const int tid  = threadIdx.x;
    const int wid  = tid >> 5;
    const int lane = tid & 31;
    const int bm   = blockIdx.x * 128;
    const int bn   = blockIdx.y * 128;
    const int wm   = (wid & 1) * 64;
    const int wn   = (wid >> 1) * 32;

    const __nv_bfloat16* WhB = Wh + (size_t)bn * K;
    const __nv_bfloat16* WlB = Wl + (size_t)bn * K;

    float acc[4][4][4];
#pragma unroll
    for (int i = 0; i < 4; i++)
#pragma unroll
        for (int j = 0; j < 4; j++)
#pragma unroll
            for (int q = 0; q < 4; q++) acc[i][j][q] = 0.0f;

    const int lrow = lane & 15;
    const int lcol = (lane >> 4) << 3;
    const uint2 z2 = make_uint2(0u, 0u);

    for (int kc = 0; kc < K; kc += 32) {
        __syncthreads();
        // A fill: 128 rows x 32 k bf16 hi/lo (uint2 = 4 bf16)
#pragma unroll
        for (int e = tid; e < 1024; e += 256) {
            int row = e >> 3, seg = (e & 7) << 2;
            size_t gi = (size_t)(bm + row) * K + kc + seg;
            bool ok = (bm + row) < M;
            *reinterpret_cast<uint2*>(&sAh[row][seg]) =
                ok ? *reinterpret_cast<const uint2*>(&Ah[gi]) : z2;
            *reinterpret_cast<uint2*>(&sAl[row][seg]) =
                ok ? *reinterpret_cast<const uint2*>(&Al[gi]) : z2;
        }
        // B fill: 128 rows x 32 k bf16 hi/lo
#pragma unroll
        for (int e = tid; e < 1024; e += 256) {
            int row = e >> 3, seg = (e & 7) << 2;
            size_t gi = (size_t)row * K + kc + seg;
            *reinterpret_cast<uint2*>(&sBh[row][seg]) = *reinterpret_cast<const uint2*>(&WhB[gi]);
            *reinterpret_cast<uint2*>(&sBl[row][seg]) = *reinterpret_cast<const uint2*>(&WlB[gi]);
        }
        __syncthreads();

#pragma unroll
        for (int ks = 0; ks < 2; ks++) {
            const int k0 = ks * 16;
            uint32_t ah[4][4], al[4][4], bh[4][2], bl[4][2];
#pragma unroll
            for (int mi = 0; mi < 4; mi++) {
                uint32_t adrh = (uint32_t)__cvta_generic_to_shared(&sAh[wm + mi * 16 + lrow][k0 + lcol]);
                uint32_t adrl = (uint32_t)__cvta_generic_to_shared(&sAl[wm + mi * 16 + lrow][k0 + lcol]);
                LDMX4(ah[mi][0], ah[mi][1], ah[mi][2], ah[mi][3], adrh);
                LDMX4(al[mi][0], al[mi][1], al[mi][2], al[mi][3], adrl);
            }
#pragma unroll
            for (int nj = 0; nj < 2; nj++) {
                uint32_t r0, r1, r2, r3;
                uint32_t adrh = (uint32_t)__cvta_generic_to_shared(&sBh[wn + nj * 16 + lrow][k0 + lcol]);
                LDMX4(r0, r1, r2, r3, adrh);
                bh[nj * 2 + 0][0] = r0; bh[nj * 2 + 0][1] = r2;
                bh[nj * 2 + 1][0] = r1; bh[nj * 2 + 1][1] = r3;
                uint32_t adrl = (uint32_t)__cvta_generic_to_shared(&sBl[wn + nj * 16 + lrow][k0 + lcol]);
                LDMX4(r0, r1, r2, r3, adrl);
                bl[nj * 2 + 0][0] = r0; bl[nj * 2 + 0][1] = r2;
                bl[nj * 2 + 1][0] = r1; bl[nj * 2 + 1][1] = r3;
            }
#pragma unroll
            for (int mi = 0; mi < 4; mi++)
#pragma unroll
                for (int nt = 0; nt < 4; nt++) {
                    MMA16816(acc[mi][nt], ah[mi], bh[nt]);
                    MMA16816(acc[mi][nt], al[mi], bh[nt]);
                    MMA16816(acc[mi][nt], ah[mi], bl[nt]);
                }
        }
    }

    // ---- epilogue ----
    const int trow = lane >> 2;
    const int tcol = (lane & 3) * 2;
#pragma unroll
    for (int mi = 0; mi < 4; mi++) {
        int r0 = bm + wm + mi * 16 + trow;
#pragma unroll
        for (int nt = 0; nt < 4; nt++) {
            int c0 = bn + wn + nt * 8 + tcol;
            if (r0 < M)
                *reinterpret_cast<float2*>(&C[(size_t)r0 * N + c0]) =
                    make_float2(acc[mi][nt][0], acc[mi][nt][1]);
            if (r0 + 8 < M)
                *reinterpret_cast<float2*>(&C[(size_t)(r0 + 8) * N + c0]) =
                    make_float2(acc[mi][nt][2], acc[mi][nt][3]);
        }
    }
}

// ---------------- 4) per-group prefix scan + bias + relu (batch-4 prefetch) ---
template <int BF16OUT>
__global__ __launch_bounds__(128) void scan_relu(const float* __restrict__ H,
                                                 const float* __restrict__ bias,
                                                 float* __restrict__ outF,
                                                 __nv_bfloat16* __restrict__ outH,
                                                 __nv_bfloat16* __restrict__ outL, int D) {
    __shared__ int   s_mem[MAXG];
    __shared__ float s_dis[MAXG];
    const int g = blockIdx.x;
    const int c = g_cnt[g];
    for (int m = threadIdx.x; m < c; m += 128) {
        int i = g_members[g * MAXG + m];
        s_mem[m] = i;
        s_dis[m] = g_dis[i];
    }
    __syncthreads();
    const int f = blockIdx.y * 128 + threadIdx.x;
    float acc = 0.0f;
    const float bf = bias[f];
    for (int m = 0; m < c; m += 4) {
        float v[4], dd[4];
        int   id[4];
#pragma unroll
        for (int j = 0; j < 4; j++) {
            if (m + j < c) {
                id[j] = s_mem[m + j];
                dd[j] = s_dis[m + j];
                v[j]  = H[(size_t)id[j] * D + f];
            }
        }
#pragma unroll
        for (int j = 0; j < 4; j++) {
            if (m + j < c) {
                acc = fmaf(dd[j], v[j], acc);
                float o = fmaxf(fmaf(dd[j], acc, bf), 0.0f);
                size_t oi = (size_t)id[j] * D + f;
                if (BF16OUT) {
                    __nv_bfloat16 h = __float2bfloat16(o);
                    outH[oi] = h;
                    outL[oi] = __float2bfloat16(o - __bfloat162float(h));
                } else {
                    outF[oi] = o;
                }
            }
        }
    }
}

// ---------------- 5) LayerNorm over last dim (128) ----------------------------
__global__ __launch_bounds__(256) void layernorm128(const float* __restrict__ h,
                                                    const float* __restrict__ gamma,
                                                    const float* __restrict__ beta,
                                                    float* __restrict__ out, int n) {
    int row = blockIdx.x * (blockDim.x >> 5) + (threadIdx.x >> 5);
    if (row >= n) return;
    int lane = threadIdx.x & 31;
    float4 v = reinterpret_cast<const float4*>(h + (size_t)row * 128)[lane];
    float s = v.x + v.y + v.z + v.w;
#pragma unroll
    for (int o = 16; o; o >>= 1) s += __shfl_xor_sync(0xffffffffu, s, o);
    float mu = s * (1.0f / 128.0f);
    float dx = v.x - mu, dy = v.y - mu, dz = v.z - mu, dw = v.w - mu;
    float q = dx * dx + dy * dy + dz * dz + dw * dw;
#pragma unroll
    for (int o = 16; o; o >>= 1) q += __shfl_xor_sync(0xffffffffu, q, o);
    float inv = rsqrtf(q * (1.0f / 128.0f) + 1e-5f);
    float4 ga = reinterpret_cast<const float4*>(gamma)[lane];
    float4 be = reinterpret_cast<const float4*>(beta)[lane];
    float4 o4;
    o4.x = fmaf(dx * inv, ga.x, be.x);
    o4.y = fmaf(dy * inv, ga.y, be.y);
    o4.z = fmaf(dz * inv, ga.z, be.z);
    o4.w = fmaf(dw * inv, ga.w, be.w);
    reinterpret_cast<float4*>(out + (size_t)row * 128)[lane] = o4;
}

// ---------------- launch ------------------------------------------------------
extern "C" void kernel_launch(void* const* d_in, const int* in_sizes, int n_in,
                              void* d_out, int out_size) {
    const float* x     = (const float*)d_in[0];
    const void*  idx   = d_in[1];
    const float* W1    = (const float*)d_in[2];
    const float* b1    = (const float*)d_in[3];
    const float* W2    = (const float*)d_in[4];
    const float* b2    = (const float*)d_in[5];
    const float* W3    = (const float*)d_in[6];
    const float* b3    = (const float*)d_in[7];
    const float* gamma = (const float*)d_in[8];
    const float* beta  = (const float*)d_in[9];
    float* out = (float*)d_out;

    float *bufA, *bufB;
    __nv_bfloat16 *actH, *actL, *w1h, *w1l, *w2h, *w2l, *w3h, *w3l;
    cudaGetSymbolAddress((void**)&bufA, g_bufA);
    cudaGetSymbolAddress((void**)&bufB, g_bufB);
    cudaGetSymbolAddress((void**)&actH, g_actH);
    cudaGetSymbolAddress((void**)&actL, g_actL);
    cudaGetSymbolAddress((void**)&w1h, g_w1h);
    cudaGetSymbolAddress((void**)&w1l, g_w1l);
    cudaGetSymbolAddress((void**)&w2h, g_w2h);
    cudaGetSymbolAddress((void**)&w2l, g_w2l);
    cudaGetSymbolAddress((void**)&w3h, g_w3h);
    cudaGetSymbolAddress((void**)&w3l, g_w3l);

    const int n = NNODES;
    const int mtiles = (n + 127) / 128;  // 157

    detect_dtype<<<1, 256>>>((const int*)idx, n);
    build_groups<<<NGROUP, 256>>>(idx, n);
    prep_w_t<<<dim3(128 / 32, 256 / 32), dim3(32, 8)>>>(W1, w1h, w1l, 128, 256);
    prep_w_t<<<dim3(256 / 32, 256 / 32), dim3(32, 8)>>>(W2, w2h, w2l, 256, 256);
    prep_w_t<<<dim3(256 / 32, 128 / 32), dim3(32, 8)>>>(W3, w3h, w3l, 256, 128);
    conv_split<<<(n * 128 / 4 + 255) / 256, 256>>>(x, actH, actL, n * 128 / 4);

    // layer 1: [20000,128] @ W1 -> bufA[20000,256]
    gemm_mma<<<dim3(mtiles, 2), 256>>>(actH, actL, w1h, w1l, bufA, n, 128, 256);
    scan_relu<1><<<dim3(NGROUP, 2), 128>>>(bufA, b1, nullptr, actH, actL, 256);
    // layer 2: [20000,256] @ W2 -> bufA
    gemm_mma<<<dim3(mtiles, 2), 256>>>(actH, actL, w2h, w2l, bufA, n, 256, 256);
    scan_relu<1><<<dim3(NGROUP, 2), 128>>>(bufA, b2, nullptr, actH, actL, 256);
    // layer 3: [20000,256] @ W3 -> bufA (N=128)
    gemm_mma<<<dim3(mtiles, 1), 256>>>(actH, actL, w3h, w3l, bufA, n, 256, 128);
    scan_relu<0><<<dim3(NGROUP, 1), 128>>>(bufA, b3, bufB, nullptr, nullptr, 128);

    layernorm128<<<(n + 7) / 8, 256>>>(bufB, gamma, beta, out, n);
}

// round 7
// speedup vs baseline: 1.1107x; 1.1107x over previous
#include <cuda_runtime.h>
#include <cuda_bf16.h>
#include <math.h>
#include <stdint.h>

#define NNODES 20000
#define NGROUP 400
#define MAXG   512

// ---------------- scratch (static device allocations; no cudaMalloc) ----------
__device__ float g_bufA[NNODES * 256];
__device__ float g_bufB[NNODES * 256];
__device__ int   g_members[NGROUP * MAXG];
__device__ int   g_cnt[NGROUP];
__device__ float g_dis[NNODES];
__device__ int   g_is64;   // 1 if idx buffer is int64, 0 if int32

// bf16 hi/lo transposed weights: [N][K] row-major
__device__ __nv_bfloat16 g_w1h[256 * 128], g_w1l[256 * 128];
__device__ __nv_bfloat16 g_w2h[256 * 256], g_w2l[256 * 256];
__device__ __nv_bfloat16 g_w3h[128 * 256], g_w3l[128 * 256];

__device__ __forceinline__ uint32_t pack_bf16x2(float a, float b) {
    __nv_bfloat162 t = __floats2bfloat162_rn(a, b);
    return *reinterpret_cast<uint32_t*>(&t);
}

// ---------------- 0) dtype detection for idx ---------------------------------
__global__ void detect_dtype(const int* __restrict__ idx32, int n) {
    int i = threadIdx.x;
    bool bad = false;
    if (i < n / 2) {
        int lo = idx32[2 * i];
        int hi = idx32[2 * i + 1];
        bad = (hi != 0) || (lo < 0) || (lo >= NGROUP);
    }
    unsigned m = __ballot_sync(0xffffffffu, bad);
    __shared__ unsigned s_any[8];
    if ((threadIdx.x & 31) == 0) s_any[threadIdx.x >> 5] = m;
    __syncthreads();
    if (threadIdx.x == 0) {
        unsigned any = 0;
#pragma unroll
        for (int w = 0; w < 8; w++) any |= s_any[w];
        g_is64 = (any == 0) ? 1 : 0;
    }
}

// ---------------- 1) group build (4 elems/thread/tile) ------------------------
__global__ __launch_bounds__(256) void build_groups(const void* __restrict__ idx_raw, int n) {
    const int g    = blockIdx.x;
    const int tid  = threadIdx.x;
    const int lane = tid & 31;
    const int warp = tid >> 5;
    const int is64 = g_is64;
    const int*       idx32 = (const int*)idx_raw;
    const long long* idx64 = (const long long*)idx_raw;

    __shared__ int warp_sums[8];
    __shared__ int s_base;
    if (tid == 0) s_base = 0;
    __syncthreads();

    for (int t0 = 0; t0 < n; t0 += 1024) {
        int i0 = t0 + tid * 4;
        int v[4];
        if (!is64 && i0 + 3 < n) {
            int4 q = *reinterpret_cast<const int4*>(&idx32[i0]);
            v[0] = q.x; v[1] = q.y; v[2] = q.z; v[3] = q.w;
        } else {
#pragma unroll
            for (int j = 0; j < 4; j++) {
                int i = i0 + j;
                v[j] = (i < n) ? (is64 ? (int)idx64[i] : idx32[i]) : -1;
            }
        }
        unsigned m[4];
#pragma unroll
        for (int j = 0; j < 4; j++) m[j] = __ballot_sync(0xffffffffu, v[j] == g);
        unsigned lt = (1u << lane) - 1u;
        int lanebase = 0, wtotal = 0;
#pragma unroll
        for (int j = 0; j < 4; j++) { lanebase += __popc(m[j] & lt); wtotal += __popc(m[j]); }
        if (lane == 0) warp_sums[warp] = wtotal;
        __syncthreads();
        int woff = 0, tile_total = 0;
#pragma unroll
        for (int w = 0; w < 8; w++) {
            if (w < warp) woff += warp_sums[w];
            tile_total += warp_sums[w];
        }
        int mycnt = 0;
#pragma unroll
        for (int j = 0; j < 4; j++) {
            if (v[j] == g) {
                int pos = s_base + woff + lanebase + mycnt;
                g_members[g * MAXG + pos] = i0 + j;
                g_dis[i0 + j] = rsqrtf((float)(pos + 1));
                mycnt++;
            }
        }
        __syncthreads();
        if (tid == 0) s_base += tile_total;
        __syncthreads();
    }
    if (tid == 0) g_cnt[g] = s_base;
}

// ---------------- 2) weight prep: transpose + bf16 hi/lo split ----------------
__global__ void prep_w(const float* __restrict__ W, __nv_bfloat16* __restrict__ oh,
                       __nv_bfloat16* __restrict__ ol, int K, int N) {
    int e = blockIdx.x * 256 + threadIdx.x;
    if (e >= K * N) return;
    int n = e / K, k = e - n * K;
    float v = W[(size_t)k * N + n];
    __nv_bfloat16 h = __float2bfloat16(v);
    oh[e] = h;
    ol[e] = __float2bfloat16(v - __bfloat162float(h));
}

// ---------------- 3) HMMA GEMM, register double-buffered mainloop -------------
// C[M,N] = A[M,K] @ W^T, A fp32, W bf16 hi/lo [N][K]; 3-split, fp32 accum.
// BM=128, BN=128, BK=32, 256 threads: warps 2(M)x4(N), warp tile 64x32.
#define LDMX4(r0, r1, r2, r3, addr) \
    asm volatile("ldmatrix.sync.aligned.m8n8.x4.shared.b16 {%0,%1,%2,%3}, [%4];" \
                 : "=r"(r0), "=r"(r1), "=r"(r2), "=r"(r3) : "r"(addr))
#define MMA16816(c, a, b) \
    asm volatile("mma.sync.aligned.m16n8k16.row.col.f32.bf16.bf16.f32 " \
                 "{%0,%1,%2,%3}, {%4,%5,%6,%7}, {%8,%9}, {%0,%1,%2,%3};" \
                 : "+f"((c)[0]), "+f"((c)[1]), "+f"((c)[2]), "+f"((c)[3]) \
                 : "r"((a)[0]), "r"((a)[1]), "r"((a)[2]), "r"((a)[3]), \
                   "r"((b)[0]), "r"((b)[1]))

__global__ __launch_bounds__(256) void gemm_mma(const float* __restrict__ A,
                                                const __nv_bfloat16* __restrict__ Wh,
                                                const __nv_bfloat16* __restrict__ Wl,
                                                float* __restrict__ C,
                                                int M, int K, int N) {
    __shared__ __nv_bfloat16 sAh[128][40];
    __shared__ __nv_bfloat16 sAl[128][40];
    __shared__ __nv_bfloat16 sBh[128][40];
    __shared__ __nv_bfloat16 sBl[128][40];

    const int tid  = threadIdx.x;
    const int wid  = tid >> 5;
    const int lane = tid & 31;
    const int bm   = blockIdx.x * 128;
    const int bn   = blockIdx.y * 128;
    const int wm   = (wid & 1) * 64;
    const int wn   = (wid >> 1) * 32;

    const __nv_bfloat16* WhB = Wh + (size_t)bn * K;
    const __nv_bfloat16* WlB = Wl + (size_t)bn * K;

    float acc[4][4][4];
#pragma unroll
    for (int i = 0; i < 4; i++)
#pragma unroll
        for (int j = 0; j < 4; j++)
#pragma unroll
            for (int q = 0; q < 4; q++) acc[i][j][q] = 0.0f;

    const int lrow = lane & 15;
    const int lcol = (lane >> 4) << 3;

    // per-thread fill coordinates (4 elements per thread per array)
    int frow[4], fseg[4];
#pragma unroll
    for (int r = 0; r < 4; r++) {
        int e = tid + r * 256;
        frow[r] = e >> 3;
        fseg[r] = (e & 7) << 2;
    }

    // staging registers for the next chunk
    float4 ra[4];
    uint2  rbh[4], rbl[4];

    // prologue: load chunk 0
#pragma unroll
    for (int r = 0; r < 4; r++) {
        int gr = bm + frow[r];
        ra[r] = (gr < M) ? *reinterpret_cast<const float4*>(&A[(size_t)gr * K + fseg[r]])
                         : make_float4(0.f, 0.f, 0.f, 0.f);
        size_t gi = (size_t)frow[r] * K + fseg[r];
        rbh[r] = *reinterpret_cast<const uint2*>(&WhB[gi]);
        rbl[r] = *reinterpret_cast<const uint2*>(&WlB[gi]);
    }

    const int nchunk = K >> 5;
    for (int c = 0; c < nchunk; c++) {
        if (c > 0) __syncthreads();   // compute(c-1) done before smem overwrite
        // store staged regs -> smem (convert A here: data long since landed)
#pragma unroll
        for (int r = 0; r < 4; r++) {
            float4 a = ra[r];
            __nv_bfloat16 h0 = __float2bfloat16(a.x), h1 = __float2bfloat16(a.y);
            __nv_bfloat16 h2 = __float2bfloat16(a.z), h3 = __float2bfloat16(a.w);
            uint2 uh, ul;
            uh.x = ((uint32_t)*(uint16_t*)&h1 << 16) | *(uint16_t*)&h0;
            uh.y = ((uint32_t)*(uint16_t*)&h3 << 16) | *(uint16_t*)&h2;
            ul.x = pack_bf16x2(a.x - __bfloat162float(h0), a.y - __bfloat162float(h1));
            ul.y = pack_bf16x2(a.z - __bfloat162float(h2), a.w - __bfloat162float(h3));
            *reinterpret_cast<uint2*>(&sAh[frow[r]][fseg[r]]) = uh;
            *reinterpret_cast<uint2*>(&sAl[frow[r]][fseg[r]]) = ul;
            *reinterpret_cast<uint2*>(&sBh[frow[r]][fseg[r]]) = rbh[r];
            *reinterpret_cast<uint2*>(&sBl[frow[r]][fseg[r]]) = rbl[r];
        }
        __syncthreads();

        // prefetch next chunk while MMAs run
        if (c + 1 < nchunk) {
            const int kc = (c + 1) << 5;
#pragma unroll
            for (int r = 0; r < 4; r++) {
                int gr = bm + frow[r];
                ra[r] = (gr < M) ? *reinterpret_cast<const float4*>(&A[(size_t)gr * K + kc + fseg[r]])
                                 : make_float4(0.f, 0.f, 0.f, 0.f);
                size_t gi = (size_t)frow[r] * K + kc + fseg[r];
                rbh[r] = *reinterpret_cast<const uint2*>(&WhB[gi]);
                rbl[r] = *reinterpret_cast<const uint2*>(&WlB[gi]);
            }
        }

#pragma unroll
        for (int ks = 0; ks < 2; ks++) {
            const int k0 = ks * 16;
            uint32_t ah[4][4], al[4][4], bh[4][2], bl[4][2];
#pragma unroll
            for (int mi = 0; mi < 4; mi++) {
                uint32_t adrh = (uint32_t)__cvta_generic_to_shared(&sAh[wm + mi * 16 + lrow][k0 + lcol]);
                uint32_t adrl = (uint32_t)__cvta_generic_to_shared(&sAl[wm + mi * 16 + lrow][k0 + lcol]);
                LDMX4(ah[mi][0], ah[mi][1], ah[mi][2], ah[mi][3], adrh);
                LDMX4(al[mi][0], al[mi][1], al[mi][2], al[mi][3], adrl);
            }
#pragma unroll
            for (int nj = 0; nj < 2; nj++) {
                uint32_t r0, r1, r2, r3;
                uint32_t adrh = (uint32_t)__cvta_generic_to_shared(&sBh[wn + nj * 16 + lrow][k0 + lcol]);
                LDMX4(r0, r1, r2, r3, adrh);
                bh[nj * 2 + 0][0] = r0; bh[nj * 2 + 0][1] = r2;
                bh[nj * 2 + 1][0] = r1; bh[nj * 2 + 1][1] = r3;
                uint32_t adrl = (uint32_t)__cvta_generic_to_shared(&sBl[wn + nj * 16 + lrow][k0 + lcol]);
                LDMX4(r0, r1, r2, r3, adrl);
                bl[nj * 2 + 0][0] = r0; bl[nj * 2 + 0][1] = r2;
                bl[nj * 2 + 1][0] = r1; bl[nj * 2 + 1][1] = r3;
            }
#pragma unroll
            for (int mi = 0; mi < 4; mi++)
#pragma unroll
                for (int nt = 0; nt < 4; nt++) {
                    MMA16816(acc[mi][nt], ah[mi], bh[nt]);
                    MMA16816(acc[mi][nt], al[mi], bh[nt]);
                    MMA16816(acc[mi][nt], ah[mi], bl[nt]);
                }
        }
    }

    // ---- epilogue ----
    const int trow = lane >> 2;
    const int tcol = (lane & 3) * 2;
#pragma unroll
    for (int mi = 0; mi < 4; mi++) {
        int r0 = bm + wm + mi * 16 + trow;
#pragma unroll
        for (int nt = 0; nt < 4; nt++) {
            int c0 = bn + wn + nt * 8 + tcol;
            if (r0 < M)
                *reinterpret_cast<float2*>(&C[(size_t)r0 * N + c0]) =
                    make_float2(acc[mi][nt][0], acc[mi][nt][1]);
            if (r0 + 8 < M)
                *reinterpret_cast<float2*>(&C[(size_t)(r0 + 8) * N + c0]) =
                    make_float2(acc[mi][nt][2], acc[mi][nt][3]);
        }
    }
}

// ---------------- 4) per-group prefix scan + bias + relu ----------------------
// grid (NGROUP, D/128), 128 threads; out[j] = relu(dis_j * prefix + b)
__global__ __launch_bounds__(128) void scan_relu(const float* __restrict__ H,
                                                 const float* __restrict__ bias,
                                                 float* __restrict__ out, int D) {
    __shared__ int   s_mem[MAXG];
    __shared__ float s_dis[MAXG];
    const int g = blockIdx.x;
    const int c = g_cnt[g];
    for (int m = threadIdx.x; m < c; m += 128) {
        int i = g_members[g * MAXG + m];
        s_mem[m] = i;
        s_dis[m] = g_dis[i];
    }
    __syncthreads();
    const int f = blockIdx.y * 128 + threadIdx.x;
    float acc = 0.0f;
    const float bf = bias[f];
    for (int m = 0; m < c; m++) {
        int   i = s_mem[m];
        float d = s_dis[m];
        acc = fmaf(d, H[(size_t)i * D + f], acc);
        out[(size_t)i * D + f] = fmaxf(fmaf(d, acc, bf), 0.0f);
    }
}

// ---------------- 5) LayerNorm over last dim (128) ----------------------------
__global__ __launch_bounds__(256) void layernorm128(const float* __restrict__ h,
                                                    const float* __restrict__ gamma,
                                                    const float* __restrict__ beta,
                                                    float* __restrict__ out, int n) {
    int row = blockIdx.x * (blockDim.x >> 5) + (threadIdx.x >> 5);
    if (row >= n) return;
    int lane = threadIdx.x & 31;
    float4 v = reinterpret_cast<const float4*>(h + (size_t)row * 128)[lane];
    float s = v.x + v.y + v.z + v.w;
#pragma unroll
    for (int o = 16; o; o >>= 1) s += __shfl_xor_sync(0xffffffffu, s, o);
    float mu = s * (1.0f / 128.0f);
    float dx = v.x - mu, dy = v.y - mu, dz = v.z - mu, dw = v.w - mu;
    float q = dx * dx + dy * dy + dz * dz + dw * dw;
#pragma unroll
    for (int o = 16; o; o >>= 1) q += __shfl_xor_sync(0xffffffffu, q, o);
    float inv = rsqrtf(q * (1.0f / 128.0f) + 1e-5f);
    float4 ga = reinterpret_cast<const float4*>(gamma)[lane];
    float4 be = reinterpret_cast<const float4*>(beta)[lane];
    float4 o4;
    o4.x = fmaf(dx * inv, ga.x, be.x);
    o4.y = fmaf(dy * inv, ga.y, be.y);
    o4.z = fmaf(dz * inv, ga.z, be.z);
    o4.w = fmaf(dw * inv, ga.w, be.w);
    reinterpret_cast<float4*>(out + (size_t)row * 128)[lane] = o4;
}

// ---------------- launch ------------------------------------------------------
extern "C" void kernel_launch(void* const* d_in, const int* in_sizes, int n_in,
                              void* d_out, int out_size) {
    const float* x     = (const float*)d_in[0];
    const void*  idx   = d_in[1];
    const float* W1    = (const float*)d_in[2];
    const float* b1    = (const float*)d_in[3];
    const float* W2    = (const float*)d_in[4];
    const float* b2    = (const float*)d_in[5];
    const float* W3    = (const float*)d_in[6];
    const float* b3    = (const float*)d_in[7];
    const float* gamma = (const float*)d_in[8];
    const float* beta  = (const float*)d_in[9];
    float* out = (float*)d_out;

    float *bufA = nullptr, *bufB = nullptr;
    __nv_bfloat16 *w1h, *w1l, *w2h, *w2l, *w3h, *w3l;
    cudaGetSymbolAddress((void**)&bufA, g_bufA);
    cudaGetSymbolAddress((void**)&bufB, g_bufB);
    cudaGetSymbolAddress((void**)&w1h, g_w1h);
    cudaGetSymbolAddress((void**)&w1l, g_w1l);
    cudaGetSymbolAddress((void**)&w2h, g_w2h);
    cudaGetSymbolAddress((void**)&w2l, g_w2l);
    cudaGetSymbolAddress((void**)&w3h, g_w3h);
    cudaGetSymbolAddress((void**)&w3l, g_w3l);

    const int n = NNODES;
    const int mtiles = (n + 127) / 128;  // 157

    detect_dtype<<<1, 256>>>((const int*)idx, n);
    build_groups<<<NGROUP, 256>>>(idx, n);
    prep_w<<<(128 * 256 + 255) / 256, 256>>>(W1, w1h, w1l, 128, 256);
    prep_w<<<(256 * 256 + 255) / 256, 256>>>(W2, w2h, w2l, 256, 256);
    prep_w<<<(256 * 128 + 255) / 256, 256>>>(W3, w3h, w3l, 256, 128);

    // layer 1: x[20000,128] @ W1 -> bufA[20000,256]
    gemm_mma<<<dim3(mtiles, 2), 256>>>(x, w1h, w1l, bufA, n, 128, 256);
    scan_relu<<<dim3(NGROUP, 2), 128>>>(bufA, b1, bufB, 256);
    // layer 2: [20000,256] @ W2 -> bufA
    gemm_mma<<<dim3(mtiles, 2), 256>>>(bufB, w2h, w2l, bufA, n, 256, 256);
    scan_relu<<<dim3(NGROUP, 2), 128>>>(bufA, b2, bufB, 256);
    // layer 3: [20000,256] @ W3 -> bufA (N=128)
    gemm_mma<<<dim3(mtiles, 1), 256>>>(bufB, w3h, w3l, bufA, n, 256, 128);
    scan_relu<<<dim3(NGROUP, 1), 128>>>(bufA, b3, bufB, 128);

    layernorm128<<<(n + 7) / 8, 256>>>(bufB, gamma, beta, out, n);
}

// round 8
// speedup vs baseline: 1.1733x; 1.0563x over previous
#include <cuda_runtime.h>
#include <cuda_bf16.h>
#include <math.h>
#include <stdint.h>

#define NNODES 20000
#define NGROUP 400
#define MAXG   512

// ---------------- scratch (static device allocations; no cudaMalloc) ----------
__device__ float g_bufA[NNODES * 256];
__device__ float g_bufB[NNODES * 256];
__device__ int   g_members[NGROUP * MAXG];
__device__ int   g_cnt[NGROUP];
__device__ float g_dis[NNODES];

// bf16 hi/lo transposed weights: [N][K] row-major
__device__ __nv_bfloat16 g_w1h[256 * 128], g_w1l[256 * 128];
__device__ __nv_bfloat16 g_w2h[256 * 256], g_w2l[256 * 256];
__device__ __nv_bfloat16 g_w3h[128 * 256], g_w3l[128 * 256];

__device__ __forceinline__ uint32_t pack_bf16x2(float a, float b) {
    __nv_bfloat162 t = __floats2bfloat162_rn(a, b);
    return *reinterpret_cast<uint32_t*>(&t);
}

// ---------------- 1) group build (4 elems/thread/tile) ------------------------
// dtype detection folded in: every block derives is64 locally from the first
// 512 int32 words (deterministic, identical across blocks).
__global__ __launch_bounds__(256) void build_groups(const void* __restrict__ idx_raw, int n) {
    const int g    = blockIdx.x;
    const int tid  = threadIdx.x;
    const int lane = tid & 31;
    const int warp = tid >> 5;
    const int*       idx32 = (const int*)idx_raw;
    const long long* idx64 = (const long long*)idx_raw;

    __shared__ int warp_sums[8];
    __shared__ int s_base;
    __shared__ unsigned s_any[8];

    // ---- local dtype detection ----
    {
        bool bad = false;
        int i = tid;
        if (i < n / 2) {
            int lo = idx32[2 * i];
            int hi = idx32[2 * i + 1];
            bad = (hi != 0) || (lo < 0) || (lo >= NGROUP);
        }
        unsigned m = __ballot_sync(0xffffffffu, bad);
        if (lane == 0) s_any[warp] = m;
    }
    if (tid == 0) s_base = 0;
    __syncthreads();
    unsigned any = 0;
#pragma unroll
    for (int w = 0; w < 8; w++) any |= s_any[w];
    const int is64 = (any == 0) ? 1 : 0;
    __syncthreads();

    for (int t0 = 0; t0 < n; t0 += 1024) {
        int i0 = t0 + tid * 4;
        int v[4];
        if (!is64 && i0 + 3 < n) {
            int4 q = *reinterpret_cast<const int4*>(&idx32[i0]);
            v[0] = q.x; v[1] = q.y; v[2] = q.z; v[3] = q.w;
        } else {
#pragma unroll
            for (int j = 0; j < 4; j++) {
                int i = i0 + j;
                v[j] = (i < n) ? (is64 ? (int)idx64[i] : idx32[i]) : -1;
            }
        }
        unsigned m[4];
#pragma unroll
        for (int j = 0; j < 4; j++) m[j] = __ballot_sync(0xffffffffu, v[j] == g);
        unsigned lt = (1u << lane) - 1u;
        int lanebase = 0, wtotal = 0;
#pragma unroll
        for (int j = 0; j < 4; j++) { lanebase += __popc(m[j] & lt); wtotal += __popc(m[j]); }
        if (lane == 0) warp_sums[warp] = wtotal;
        __syncthreads();
        int woff = 0, tile_total = 0;
#pragma unroll
        for (int w = 0; w < 8; w++) {
            if (w < warp) woff += warp_sums[w];
            tile_total += warp_sums[w];
        }
        int mycnt = 0;
#pragma unroll
        for (int j = 0; j < 4; j++) {
            if (v[j] == g) {
                int pos = s_base + woff + lanebase + mycnt;
                g_members[g * MAXG + pos] = i0 + j;
                g_dis[i0 + j] = rsqrtf((float)(pos + 1));
                mycnt++;
            }
        }
        __syncthreads();
        if (tid == 0) s_base += tile_total;
        __syncthreads();
    }
    if (tid == 0) g_cnt[g] = s_base;
}

// ---------------- 2) weight prep: ALL three weights in one launch -------------
// segment 0: W1 (K=128,N=256) elems 0..32767
// segment 1: W2 (K=256,N=256) elems 0..65535
// segment 2: W3 (K=256,N=128) elems 0..32767
__global__ void prep_w_all(const float* __restrict__ W1, const float* __restrict__ W2,
                           const float* __restrict__ W3) {
    int e = blockIdx.x * 256 + threadIdx.x;
    const float* W;
    __nv_bfloat16 *oh, *ol;
    int K, N;
    if (e < 32768)            { W = W1; oh = g_w1h; ol = g_w1l; K = 128; N = 256; }
    else if (e < 32768 + 65536) { e -= 32768; W = W2; oh = g_w2h; ol = g_w2l; K = 256; N = 256; }
    else                      { e -= 32768 + 65536; W = W3; oh = g_w3h; ol = g_w3l; K = 256; N = 128; }
    int n = e / K, k = e - n * K;
    float v = W[(size_t)k * N + n];
    __nv_bfloat16 h = __float2bfloat16(v);
    oh[e] = h;
    ol[e] = __float2bfloat16(v - __bfloat162float(h));
}

// ---------------- 3) HMMA GEMM (exact R4 kernel — proven fastest) -------------
#define LDMX4(r0, r1, r2, r3, addr) \
    asm volatile("ldmatrix.sync.aligned.m8n8.x4.shared.b16 {%0,%1,%2,%3}, [%4];" \
                 : "=r"(r0), "=r"(r1), "=r"(r2), "=r"(r3) : "r"(addr))
#define MMA16816(c, a, b) \
    asm volatile("mma.sync.aligned.m16n8k16.row.col.f32.bf16.bf16.f32 " \
                 "{%0,%1,%2,%3}, {%4,%5,%6,%7}, {%8,%9}, {%0,%1,%2,%3};" \
                 : "+f"((c)[0]), "+f"((c)[1]), "+f"((c)[2]), "+f"((c)[3]) \
                 : "r"((a)[0]), "r"((a)[1]), "r"((a)[2]), "r"((a)[3]), \
                   "r"((b)[0]), "r"((b)[1]))

__global__ __launch_bounds__(256) void gemm_mma(const float* __restrict__ A,
                                                const __nv_bfloat16* __restrict__ Wh,
                                                const __nv_bfloat16* __restrict__ Wl,
                                                float* __restrict__ C,
                                                int M, int K, int N) {
    __shared__ __nv_bfloat16 sAh[128][40];
    __shared__ __nv_bfloat16 sAl[128][40];
    __shared__ __nv_bfloat16 sBh[128][40];
    __shared__ __nv_bfloat16 sBl[128][40];

    const int tid  = threadIdx.x;
    const int wid  = tid >> 5;
    const int lane = tid & 31;
    const int bm   = blockIdx.x * 128;
    const int bn   = blockIdx.y * 128;
    const int wm   = (wid & 1) * 64;
    const int wn   = (wid >> 1) * 32;

    const __nv_bfloat16* WhB = Wh + (size_t)bn * K;
    const __nv_bfloat16* WlB = Wl + (size_t)bn * K;

    float acc[4][4][4];
#pragma unroll
    for (int i = 0; i < 4; i++)
#pragma unroll
        for (int j = 0; j < 4; j++)
#pragma unroll
            for (int q = 0; q < 4; q++) acc[i][j][q] = 0.0f;

    const int lrow = lane & 15;
    const int lcol = (lane >> 4) << 3;

    for (int kc = 0; kc < K; kc += 32) {
        __syncthreads();
#pragma unroll
        for (int e = tid; e < 1024; e += 256) {
            int row = e >> 3, seg = (e & 7) << 2;
            float4 a = make_float4(0.f, 0.f, 0.f, 0.f);
            int gr = bm + row;
            if (gr < M) a = *reinterpret_cast<const float4*>(&A[(size_t)gr * K + kc + seg]);
            __nv_bfloat16 h0 = __float2bfloat16(a.x), h1 = __float2bfloat16(a.y);
            __nv_bfloat16 h2 = __float2bfloat16(a.z), h3 = __float2bfloat16(a.w);
            uint2 uh, ul;
            uh.x = ((uint32_t)*(uint16_t*)&h1 << 16) | *(uint16_t*)&h0;
            uh.y = ((uint32_t)*(uint16_t*)&h3 << 16) | *(uint16_t*)&h2;
            ul.x = pack_bf16x2(a.x - __bfloat162float(h0), a.y - __bfloat162float(h1));
            ul.y = pack_bf16x2(a.z - __bfloat162float(h2), a.w - __bfloat162float(h3));
            *reinterpret_cast<uint2*>(&sAh[row][seg]) = uh;
            *reinterpret_cast<uint2*>(&sAl[row][seg]) = ul;
        }
#pragma unroll
        for (int e = tid; e < 1024; e += 256) {
            int row = e >> 3, seg = (e & 7) << 2;
            size_t gi = (size_t)row * K + kc + seg;
            *reinterpret_cast<uint2*>(&sBh[row][seg]) = *reinterpret_cast<const uint2*>(&WhB[gi]);
            *reinterpret_cast<uint2*>(&sBl[row][seg]) = *reinterpret_cast<const uint2*>(&WlB[gi]);
        }
        __syncthreads();

#pragma unroll
        for (int ks = 0; ks < 2; ks++) {
            const int k0 = ks * 16;
            uint32_t ah[4][4], al[4][4], bh[4][2], bl[4][2];
#pragma unroll
            for (int mi = 0; mi < 4; mi++) {
                uint32_t adrh = (uint32_t)__cvta_generic_to_shared(&sAh[wm + mi * 16 + lrow][k0 + lcol]);
                uint32_t adrl = (uint32_t)__cvta_generic_to_shared(&sAl[wm + mi * 16 + lrow][k0 + lcol]);
                LDMX4(ah[mi][0], ah[mi][1], ah[mi][2], ah[mi][3], adrh);
                LDMX4(al[mi][0], al[mi][1], al[mi][2], al[mi][3], adrl);
            }
#pragma unroll
            for (int nj = 0; nj < 2; nj++) {
                uint32_t r0, r1, r2, r3;
                uint32_t adrh = (uint32_t)__cvta_generic_to_shared(&sBh[wn + nj * 16 + lrow][k0 + lcol]);
                LDMX4(r0, r1, r2, r3, adrh);
                bh[nj * 2 + 0][0] = r0; bh[nj * 2 + 0][1] = r2;
                bh[nj * 2 + 1][0] = r1; bh[nj * 2 + 1][1] = r3;
                uint32_t adrl = (uint32_t)__cvta_generic_to_shared(&sBl[wn + nj * 16 + lrow][k0 + lcol]);
                LDMX4(r0, r1, r2, r3, adrl);
                bl[nj * 2 + 0][0] = r0; bl[nj * 2 + 0][1] = r2;
                bl[nj * 2 + 1][0] = r1; bl[nj * 2 + 1][1] = r3;
            }
#pragma unroll
            for (int mi = 0; mi < 4; mi++)
#pragma unroll
                for (int nt = 0; nt < 4; nt++) {
                    MMA16816(acc[mi][nt], ah[mi], bh[nt]);
                    MMA16816(acc[mi][nt], al[mi], bh[nt]);
                    MMA16816(acc[mi][nt], ah[mi], bl[nt]);
                }
        }
    }

    const int trow = lane >> 2;
    const int tcol = (lane & 3) * 2;
#pragma unroll
    for (int mi = 0; mi < 4; mi++) {
        int r0 = bm + wm + mi * 16 + trow;
#pragma unroll
        for (int nt = 0; nt < 4; nt++) {
            int c0 = bn + wn + nt * 8 + tcol;
            if (r0 < M)
                *reinterpret_cast<float2*>(&C[(size_t)r0 * N + c0]) =
                    make_float2(acc[mi][nt][0], acc[mi][nt][1]);
            if (r0 + 8 < M)
                *reinterpret_cast<float2*>(&C[(size_t)(r0 + 8) * N + c0]) =
                    make_float2(acc[mi][nt][2], acc[mi][nt][3]);
        }
    }
}

// ---------------- 4) per-group prefix scan + bias + relu (quad-batched) -------
// grid (NGROUP, D/128), 128 threads. Same arithmetic order as R4 (quad loads
// are hoisted only; fma chain sequential) -> bitwise-identical results.
__global__ __launch_bounds__(128) void scan_relu(const float* __restrict__ H,
                                                 const float* __restrict__ bias,
                                                 float* __restrict__ out, int D) {
    __shared__ int   s_mem[MAXG];
    __shared__ float s_dis[MAXG];
    const int g = blockIdx.x;
    const int c = g_cnt[g];
    for (int m = threadIdx.x; m < c; m += 128) {
        int i = g_members[g * MAXG + m];
        s_mem[m] = i;
        s_dis[m] = g_dis[i];
    }
    __syncthreads();
    const int f = blockIdx.y * 128 + threadIdx.x;
    float acc = 0.0f;
    const float bf = bias[f];
    int m = 0;
    for (; m + 4 <= c; m += 4) {
        int   id0 = s_mem[m + 0], id1 = s_mem[m + 1], id2 = s_mem[m + 2], id3 = s_mem[m + 3];
        float d0 = s_dis[m + 0], d1 = s_dis[m + 1], d2 = s_dis[m + 2], d3 = s_dis[m + 3];
        float v0 = __ldg(&H[(size_t)id0 * D + f]);
        float v1 = __ldg(&H[(size_t)id1 * D + f]);
        float v2 = __ldg(&H[(size_t)id2 * D + f]);
        float v3 = __ldg(&H[(size_t)id3 * D + f]);
        acc = fmaf(d0, v0, acc);
        out[(size_t)id0 * D + f] = fmaxf(fmaf(d0, acc, bf), 0.0f);
        acc = fmaf(d1, v1, acc);
        out[(size_t)id1 * D + f] = fmaxf(fmaf(d1, acc, bf), 0.0f);
        acc = fmaf(d2, v2, acc);
        out[(size_t)id2 * D + f] = fmaxf(fmaf(d2, acc, bf), 0.0f);
        acc = fmaf(d3, v3, acc);
        out[(size_t)id3 * D + f] = fmaxf(fmaf(d3, acc, bf), 0.0f);
    }
    for (; m < c; m++) {
        int   i = s_mem[m];
        float d = s_dis[m];
        acc = fmaf(d, __ldg(&H[(size_t)i * D + f]), acc);
        out[(size_t)i * D + f] = fmaxf(fmaf(d, acc, bf), 0.0f);
    }
}

// ---------------- 5) LayerNorm over last dim (128) ----------------------------
__global__ __launch_bounds__(256) void layernorm128(const float* __restrict__ h,
                                                    const float* __restrict__ gamma,
                                                    const float* __restrict__ beta,
                                                    float* __restrict__ out, int n) {
    int row = blockIdx.x * (blockDim.x >> 5) + (threadIdx.x >> 5);
    if (row >= n) return;
    int lane = threadIdx.x & 31;
    float4 v = reinterpret_cast<const float4*>(h + (size_t)row * 128)[lane];
    float s = v.x + v.y + v.z + v.w;
#pragma unroll
    for (int o = 16; o; o >>= 1) s += __shfl_xor_sync(0xffffffffu, s, o);
    float mu = s * (1.0f / 128.0f);
    float dx = v.x - mu, dy = v.y - mu, dz = v.z - mu, dw = v.w - mu;
    float q = dx * dx + dy * dy + dz * dz + dw * dw;
#pragma unroll
    for (int o = 16; o; o >>= 1) q += __shfl_xor_sync(0xffffffffu, q, o);
    float inv = rsqrtf(q * (1.0f / 128.0f) + 1e-5f);
    float4 ga = reinterpret_cast<const float4*>(gamma)[lane];
    float4 be = reinterpret_cast<const float4*>(beta)[lane];
    float4 o4;
    o4.x = fmaf(dx * inv, ga.x, be.x);
    o4.y = fmaf(dy * inv, ga.y, be.y);
    o4.z = fmaf(dz * inv, ga.z, be.z);
    o4.w = fmaf(dw * inv, ga.w, be.w);
    reinterpret_cast<float4*>(out + (size_t)row * 128)[lane] = o4;
}

// ---------------- launch ------------------------------------------------------
extern "C" void kernel_launch(void* const* d_in, const int* in_sizes, int n_in,
                              void* d_out, int out_size) {
    const float* x     = (const float*)d_in[0];
    const void*  idx   = d_in[1];
    const float* W1    = (const float*)d_in[2];
    const float* b1    = (const float*)d_in[3];
    const float* W2    = (const float*)d_in[4];
    const float* b2    = (const float*)d_in[5];
    const float* W3    = (const float*)d_in[6];
    const float* b3    = (const float*)d_in[7];
    const float* gamma = (const float*)d_in[8];
    const float* beta  = (const float*)d_in[9];
    float* out = (float*)d_out;

    float *bufA = nullptr, *bufB = nullptr;
    __nv_bfloat16 *w1h, *w1l, *w2h, *w2l, *w3h, *w3l;
    cudaGetSymbolAddress((void**)&bufA, g_bufA);
    cudaGetSymbolAddress((void**)&bufB, g_bufB);
    cudaGetSymbolAddress((void**)&w1h, g_w1h);
    cudaGetSymbolAddress((void**)&w1l, g_w1l);
    cudaGetSymbolAddress((void**)&w2h, g_w2h);
    cudaGetSymbolAddress((void**)&w2l, g_w2l);
    cudaGetSymbolAddress((void**)&w3h, g_w3h);
    cudaGetSymbolAddress((void**)&w3l, g_w3l);

    const int n = NNODES;
    const int mtiles = (n + 127) / 128;  // 157

    build_groups<<<NGROUP, 256>>>(idx, n);
    prep_w_all<<<(32768 + 65536 + 32768) / 256, 256>>>(W1, W2, W3);

    // layer 1: x[20000,128] @ W1 -> bufA[20000,256]
    gemm_mma<<<dim3(mtiles, 2), 256>>>(x, w1h, w1l, bufA, n, 128, 256);
    scan_relu<<<dim3(NGROUP, 2), 128>>>(bufA, b1, bufB, 256);
    // layer 2: [20000,256] @ W2 -> bufA
    gemm_mma<<<dim3(mtiles, 2), 256>>>(bufB, w2h, w2l, bufA, n, 256, 256);
    scan_relu<<<dim3(NGROUP, 2), 128>>>(bufA, b2, bufB, 256);
    // layer 3: [20000,256] @ W3 -> bufA (N=128)
    gemm_mma<<<dim3(mtiles, 1), 256>>>(bufB, w3h, w3l, bufA, n, 256, 128);
    scan_relu<<<dim3(NGROUP, 1), 128>>>(bufA, b3, bufB, 128);

    layernorm128<<<(n + 7) / 8, 256>>>(bufB, gamma, beta, out, n);
}

// round 12
// speedup vs baseline: 1.1789x; 1.0048x over previous
#include <cuda_runtime.h>
#include <cuda_bf16.h>
#include <math.h>
#include <stdint.h>

#define NNODES 20000
#define NGROUP 400
#define MAXG   512

// ---------------- scratch (static device allocations; no cudaMalloc) ----------
__device__ float g_bufA[NNODES * 256];
__device__ float g_bufB[NNODES * 256];
__device__ int   g_members[NGROUP * MAXG];
__device__ int   g_cnt[NGROUP];
__device__ float g_dis[NNODES];

// bf16 hi/lo transposed weights: [N][K] row-major (16B-aligned for cp.async)
__device__ __align__(16) __nv_bfloat16 g_w1h[256 * 128], g_w1l[256 * 128];
__device__ __align__(16) __nv_bfloat16 g_w2h[256 * 256], g_w2l[256 * 256];
__device__ __align__(16) __nv_bfloat16 g_w3h[128 * 256], g_w3l[128 * 256];

__device__ __forceinline__ uint32_t pack_bf16x2(float a, float b) {
    __nv_bfloat162 t = __floats2bfloat162_rn(a, b);
    return *reinterpret_cast<uint32_t*>(&t);
}

__device__ __forceinline__ void cp_async16(uint32_t saddr, const void* gptr) {
    asm volatile("cp.async.cg.shared.global [%0], [%1], 16;" :: "r"(saddr), "l"(gptr));
}
#define CP_COMMIT() asm volatile("cp.async.commit_group;" ::: "memory")
#define CP_WAIT0()  asm volatile("cp.async.wait_group 0;" ::: "memory")

// ---------------- 1) group build (4 elems/thread/tile) ------------------------
// dtype detection folded in: every block derives is64 locally.
__global__ __launch_bounds__(256) void build_groups(const void* __restrict__ idx_raw, int n) {
    const int g    = blockIdx.x;
    const int tid  = threadIdx.x;
    const int lane = tid & 31;
    const int warp = tid >> 5;
    const int*       idx32 = (const int*)idx_raw;
    const long long* idx64 = (const long long*)idx_raw;

    __shared__ int warp_sums[8];
    __shared__ int s_base;
    __shared__ unsigned s_any[8];

    {
        bool bad = false;
        int i = tid;
        if (i < n / 2) {
            int lo = idx32[2 * i];
            int hi = idx32[2 * i + 1];
            bad = (hi != 0) || (lo < 0) || (lo >= NGROUP);
        }
        unsigned m = __ballot_sync(0xffffffffu, bad);
        if (lane == 0) s_any[warp] = m;
    }
    if (tid == 0) s_base = 0;
    __syncthreads();
    unsigned any = 0;
#pragma unroll
    for (int w = 0; w < 8; w++) any |= s_any[w];
    const int is64 = (any == 0) ? 1 : 0;
    __syncthreads();

    for (int t0 = 0; t0 < n; t0 += 1024) {
        int i0 = t0 + tid * 4;
        int v[4];
        if (!is64 && i0 + 3 < n) {
            int4 q = *reinterpret_cast<const int4*>(&idx32[i0]);
            v[0] = q.x; v[1] = q.y; v[2] = q.z; v[3] = q.w;
        } else {
#pragma unroll
            for (int j = 0; j < 4; j++) {
                int i = i0 + j;
                v[j] = (i < n) ? (is64 ? (int)idx64[i] : idx32[i]) : -1;
            }
        }
        unsigned m[4];
#pragma unroll
        for (int j = 0; j < 4; j++) m[j] = __ballot_sync(0xffffffffu, v[j] == g);
        unsigned lt = (1u << lane) - 1u;
        int lanebase = 0, wtotal = 0;
#pragma unroll
        for (int j = 0; j < 4; j++) { lanebase += __popc(m[j] & lt); wtotal += __popc(m[j]); }
        if (lane == 0) warp_sums[warp] = wtotal;
        __syncthreads();
        int woff = 0, tile_total = 0;
#pragma unroll
        for (int w = 0; w < 8; w++) {
            if (w < warp) woff += warp_sums[w];
            tile_total += warp_sums[w];
        }
        int mycnt = 0;
#pragma unroll
        for (int j = 0; j < 4; j++) {
            if (v[j] == g) {
                int pos = s_base + woff + lanebase + mycnt;
                g_members[g * MAXG + pos] = i0 + j;
                g_dis[i0 + j] = rsqrtf((float)(pos + 1));
                mycnt++;
            }
        }
        __syncthreads();
        if (tid == 0) s_base += tile_total;
        __syncthreads();
    }
    if (tid == 0) g_cnt[g] = s_base;
}

// ---------------- 2) weight prep: ALL three weights in one launch -------------
__global__ void prep_w_all(const float* __restrict__ W1, const float* __restrict__ W2,
                           const float* __restrict__ W3) {
    int e = blockIdx.x * 256 + threadIdx.x;
    const float* W;
    __nv_bfloat16 *oh, *ol;
    int K, N;
    if (e < 32768)            { W = W1; oh = g_w1h; ol = g_w1l; K = 128; N = 256; }
    else if (e < 32768 + 65536) { e -= 32768; W = W2; oh = g_w2h; ol = g_w2l; K = 256; N = 256; }
    else                      { e -= 32768 + 65536; W = W3; oh = g_w3h; ol = g_w3l; K = 256; N = 128; }
    int n = e / K, k = e - n * K;
    float v = W[(size_t)k * N + n];
    __nv_bfloat16 h = __float2bfloat16(v);
    oh[e] = h;
    ol[e] = __float2bfloat16(v - __bfloat162float(h));
}

// ---------------- 3) HMMA GEMM (R4 shape; B tiles via cp.async) ---------------
#define LDMX4(r0, r1, r2, r3, addr) \
    asm volatile("ldmatrix.sync.aligned.m8n8.x4.shared.b16 {%0,%1,%2,%3}, [%4];" \
                 : "=r"(r0), "=r"(r1), "=r"(r2), "=r"(r3) : "r"(addr))
#define MMA16816(c, a, b) \
    asm volatile("mma.sync.aligned.m16n8k16.row.col.f32.bf16.bf16.f32 " \
                 "{%0,%1,%2,%3}, {%4,%5,%6,%7}, {%8,%9}, {%0,%1,%2,%3};" \
                 : "+f"((c)[0]), "+f"((c)[1]), "+f"((c)[2]), "+f"((c)[3]) \
                 : "r"((a)[0]), "r"((a)[1]), "r"((a)[2]), "r"((a)[3]), \
                   "r"((b)[0]), "r"((b)[1]))

__global__ __launch_bounds__(256) void gemm_mma(const float* __restrict__ A,
                                                const __nv_bfloat16* __restrict__ Wh,
                                                const __nv_bfloat16* __restrict__ Wl,
                                                float* __restrict__ C,
                                                int M, int K, int N) {
    __shared__ __align__(16) __nv_bfloat16 sAh[128][40];
    __shared__ __align__(16) __nv_bfloat16 sAl[128][40];
    __shared__ __align__(16) __nv_bfloat16 sBh[128][40];
    __shared__ __align__(16) __nv_bfloat16 sBl[128][40];

    const int tid  = threadIdx.x;
    const int wid  = tid >> 5;
    const int lane = tid & 31;
    const int bm   = blockIdx.x * 128;
    const int bn   = blockIdx.y * 128;
    const int wm   = (wid & 1) * 64;
    const int wn   = (wid >> 1) * 32;

    const __nv_bfloat16* WhB = Wh + (size_t)bn * K;
    const __nv_bfloat16* WlB = Wl + (size_t)bn * K;

    float acc[4][4][4];
#pragma unroll
    for (int i = 0; i < 4; i++)
#pragma unroll
        for (int j = 0; j < 4; j++)
#pragma unroll
            for (int q = 0; q < 4; q++) acc[i][j][q] = 0.0f;

    const int lrow = lane & 15;
    const int lcol = (lane >> 4) << 3;

    // cp.async fill coordinates for B: 512 x 16B per array, 2 per thread each
    const int brow0 = tid >> 2,            bseg0 = (tid & 3) << 3;          // e = tid
    const int brow1 = (tid + 256) >> 2,    bseg1 = ((tid + 256) & 3) << 3;  // e = tid+256

    for (int kc = 0; kc < K; kc += 32) {
        __syncthreads();
        // ---- B fill via cp.async (in flight while A converts) ----
        cp_async16((uint32_t)__cvta_generic_to_shared(&sBh[brow0][bseg0]), &WhB[(size_t)brow0 * K + kc + bseg0]);
        cp_async16((uint32_t)__cvta_generic_to_shared(&sBh[brow1][bseg1]), &WhB[(size_t)brow1 * K + kc + bseg1]);
        cp_async16((uint32_t)__cvta_generic_to_shared(&sBl[brow0][bseg0]), &WlB[(size_t)brow0 * K + kc + bseg0]);
        cp_async16((uint32_t)__cvta_generic_to_shared(&sBl[brow1][bseg1]), &WlB[(size_t)brow1 * K + kc + bseg1]);
        CP_COMMIT();
        // ---- A fill: 128 rows x 32 k fp32 -> bf16 hi/lo ----
#pragma unroll
        for (int e = tid; e < 1024; e += 256) {
            int row = e >> 3, seg = (e & 7) << 2;
            float4 a = make_float4(0.f, 0.f, 0.f, 0.f);
            int gr = bm + row;
            if (gr < M) a = *reinterpret_cast<const float4*>(&A[(size_t)gr * K + kc + seg]);
            __nv_bfloat16 h0 = __float2bfloat16(a.x), h1 = __float2bfloat16(a.y);
            __nv_bfloat16 h2 = __float2bfloat16(a.z), h3 = __float2bfloat16(a.w);
            uint2 uh, ul;
            uh.x = ((uint32_t)*(uint16_t*)&h1 << 16) | *(uint16_t*)&h0;
            uh.y = ((uint32_t)*(uint16_t*)&h3 << 16) | *(uint16_t*)&h2;
            ul.x = pack_bf16x2(a.x - __bfloat162float(h0), a.y - __bfloat162float(h1));
            ul.y = pack_bf16x2(a.z - __bfloat162float(h2), a.w - __bfloat162float(h3));
            *reinterpret_cast<uint2*>(&sAh[row][seg]) = uh;
            *reinterpret_cast<uint2*>(&sAl[row][seg]) = ul;
        }
        CP_WAIT0();
        __syncthreads();

#pragma unroll
        for (int ks = 0; ks < 2; ks++) {
            const int k0 = ks * 16;
            uint32_t ah[4][4], al[4][4], bh[4][2], bl[4][2];
#pragma unroll
            for (int mi = 0; mi < 4; mi++) {
                uint32_t adrh = (uint32_t)__cvta_generic_to_shared(&sAh[wm + mi * 16 + lrow][k0 + lcol]);
                uint32_t adrl = (uint32_t)__cvta_generic_to_shared(&sAl[wm + mi * 16 + lrow][k0 + lcol]);
                LDMX4(ah[mi][0], ah[mi][1], ah[mi][2], ah[mi][3], adrh);
                LDMX4(al[mi][0], al[mi][1], al[mi][2], al[mi][3], adrl);
            }
#pragma unroll
            for (int nj = 0; nj < 2; nj++) {
                uint32_t r0, r1, r2, r3;
                uint32_t adrh = (uint32_t)__cvta_generic_to_shared(&sBh[wn + nj * 16 + lrow][k0 + lcol]);
                LDMX4(r0, r1, r2, r3, adrh);
                bh[nj * 2 + 0][0] = r0; bh[nj * 2 + 0][1] = r2;
                bh[nj * 2 + 1][0] = r1; bh[nj * 2 + 1][1] = r3;
                uint32_t adrl = (uint32_t)__cvta_generic_to_shared(&sBl[wn + nj * 16 + lrow][k0 + lcol]);
                LDMX4(r0, r1, r2, r3, adrl);
                bl[nj * 2 + 0][0] = r0; bl[nj * 2 + 0][1] = r2;
                bl[nj * 2 + 1][0] = r1; bl[nj * 2 + 1][1] = r3;
            }
#pragma unroll
            for (int mi = 0; mi < 4; mi++)
#pragma unroll
                for (int nt = 0; nt < 4; nt++) {
                    MMA16816(acc[mi][nt], ah[mi], bh[nt]);
                    MMA16816(acc[mi][nt], al[mi], bh[nt]);
                    MMA16816(acc[mi][nt], ah[mi], bl[nt]);
                }
        }
    }

    const int trow = lane >> 2;
    const int tcol = (lane & 3) * 2;
#pragma unroll
    for (int mi = 0; mi < 4; mi++) {
        int r0 = bm + wm + mi * 16 + trow;
#pragma unroll
        for (int nt = 0; nt < 4; nt++) {
            int c0 = bn + wn + nt * 8 + tcol;
            if (r0 < M)
                *reinterpret_cast<float2*>(&C[(size_t)r0 * N + c0]) =
                    make_float2(acc[mi][nt][0], acc[mi][nt][1]);
            if (r0 + 8 < M)
                *reinterpret_cast<float2*>(&C[(size_t)(r0 + 8) * N + c0]) =
                    make_float2(acc[mi][nt][2], acc[mi][nt][3]);
        }
    }
}

// ---------------- 4) per-group prefix scan + bias + relu (quad-batched) -------
__global__ __launch_bounds__(128) void scan_relu(const float* __restrict__ H,
                                                 const float* __restrict__ bias,
                                                 float* __restrict__ out, int D) {
    __shared__ int   s_mem[MAXG];
    __shared__ float s_dis[MAXG];
    const int g = blockIdx.x;
    const int c = g_cnt[g];
    for (int m = threadIdx.x; m < c; m += 128) {
        int i = g_members[g * MAXG + m];
        s_mem[m] = i;
        s_dis[m] = g_dis[i];
    }
    __syncthreads();
    const int f = blockIdx.y * 128 + threadIdx.x;
    float acc = 0.0f;
    const float bf = bias[f];
    int m = 0;
    for (; m + 4 <= c; m += 4) {
        int   id0 = s_mem[m + 0], id1 = s_mem[m + 1], id2 = s_mem[m + 2], id3 = s_mem[m + 3];
        float d0 = s_dis[m + 0], d1 = s_dis[m + 1], d2 = s_dis[m + 2], d3 = s_dis[m + 3];
        float v0 = __ldg(&H[(size_t)id0 * D + f]);
        float v1 = __ldg(&H[(size_t)id1 * D + f]);
        float v2 = __ldg(&H[(size_t)id2 * D + f]);
        float v3 = __ldg(&H[(size_t)id3 * D + f]);
        acc = fmaf(d0, v0, acc);
        out[(size_t)id0 * D + f] = fmaxf(fmaf(d0, acc, bf), 0.0f);
        acc = fmaf(d1, v1, acc);
        out[(size_t)id1 * D + f] = fmaxf(fmaf(d1, acc, bf), 0.0f);
        acc = fmaf(d2, v2, acc);
        out[(size_t)id2 * D + f] = fmaxf(fmaf(d2, acc, bf), 0.0f);
        acc = fmaf(d3, v3, acc);
        out[(size_t)id3 * D + f] = fmaxf(fmaf(d3, acc, bf), 0.0f);
    }
    for (; m < c; m++) {
        int   i = s_mem[m];
        float d = s_dis[m];
        acc = fmaf(d, __ldg(&H[(size_t)i * D + f]), acc);
        out[(size_t)i * D + f] = fmaxf(fmaf(d, acc, bf), 0.0f);
    }
}

// ---------------- 5) LayerNorm over last dim (128) ----------------------------
__global__ __launch_bounds__(256) void layernorm128(const float* __restrict__ h,
                                                    const float* __restrict__ gamma,
                                                    const float* __restrict__ beta,
                                                    float* __restrict__ out, int n) {
    int row = blockIdx.x * (blockDim.x >> 5) + (threadIdx.x >> 5);
    if (row >= n) return;
    int lane = threadIdx.x & 31;
    float4 v = reinterpret_cast<const float4*>(h + (size_t)row * 128)[lane];
    float s = v.x + v.y + v.z + v.w;
#pragma unroll
    for (int o = 16; o; o >>= 1) s += __shfl_xor_sync(0xffffffffu, s, o);
    float mu = s * (1.0f / 128.0f);
    float dx = v.x - mu, dy = v.y - mu, dz = v.z - mu, dw = v.w - mu;
    float q = dx * dx + dy * dy + dz * dz + dw * dw;
#pragma unroll
    for (int o = 16; o; o >>= 1) q += __shfl_xor_sync(0xffffffffu, q, o);
    float inv = rsqrtf(q * (1.0f / 128.0f) + 1e-5f);
    float4 ga = reinterpret_cast<const float4*>(gamma)[lane];
    float4 be = reinterpret_cast<const float4*>(beta)[lane];
    float4 o4;
    o4.x = fmaf(dx * inv, ga.x, be.x);
    o4.y = fmaf(dy * inv, ga.y, be.y);
    o4.z = fmaf(dz * inv, ga.z, be.z);
    o4.w = fmaf(dw * inv, ga.w, be.w);
    reinterpret_cast<float4*>(out + (size_t)row * 128)[lane] = o4;
}

// ---------------- launch ------------------------------------------------------
extern "C" void kernel_launch(void* const* d_in, const int* in_sizes, int n_in,
                              void* d_out, int out_size) {
    const float* x     = (const float*)d_in[0];
    const void*  idx   = d_in[1];
    const float* W1    = (const float*)d_in[2];
    const float* b1    = (const float*)d_in[3];
    const float* W2    = (const float*)d_in[4];
    const float* b2    = (const float*)d_in[5];
    const float* W3    = (const float*)d_in[6];
    const float* b3    = (const float*)d_in[7];
    const float* gamma = (const float*)d_in[8];
    const float* beta  = (const float*)d_in[9];
    float* out = (float*)d_out;

    float *bufA = nullptr, *bufB = nullptr;
    __nv_bfloat16 *w1h, *w1l, *w2h, *w2l, *w3h, *w3l;
    cudaGetSymbolAddress((void**)&bufA, g_bufA);
    cudaGetSymbolAddress((void**)&bufB, g_bufB);
    cudaGetSymbolAddress((void**)&w1h, g_w1h);
    cudaGetSymbolAddress((void**)&w1l, g_w1l);
    cudaGetSymbolAddress((void**)&w2h, g_w2h);
    cudaGetSymbolAddress((void**)&w2l, g_w2l);
    cudaGetSymbolAddress((void**)&w3h, g_w3h);
    cudaGetSymbolAddress((void**)&w3l, g_w3l);

    const int n = NNODES;
    const int mtiles = (n + 127) / 128;  // 157

    build_groups<<<NGROUP, 256>>>(idx, n);
    prep_w_all<<<(32768 + 65536 + 32768) / 256, 256>>>(W1, W2, W3);

    // layer 1: x[20000,128] @ W1 -> bufA[20000,256]
    gemm_mma<<<dim3(mtiles, 2), 256>>>(x, w1h, w1l, bufA, n, 128, 256);
    scan_relu<<<dim3(NGROUP, 2), 128>>>(bufA, b1, bufB, 256);
    // layer 2: [20000,256] @ W2 -> bufA
    gemm_mma<<<dim3(mtiles, 2), 256>>>(bufB, w2h, w2l, bufA, n, 256, 256);
    scan_relu<<<dim3(NGROUP, 2), 128>>>(bufA, b2, bufB, 256);
    // layer 3: [20000,256] @ W3 -> bufA (N=128)
    gemm_mma<<<dim3(mtiles, 1), 256>>>(bufB, w3h, w3l, bufA, n, 256, 128);
    scan_relu<<<dim3(NGROUP, 1), 128>>>(bufA, b3, bufB, 128);

    layernorm128<<<(n + 7) / 8, 256>>>(bufB, gamma, beta, out, n);
}

// round 14
// speedup vs baseline: 1.2014x; 1.0192x over previous
#include <cuda_runtime.h>
#include <cuda_bf16.h>
#include <math.h>
#include <stdint.h>

#define NNODES 20000
#define NGROUP 400
#define MAXG   512

// ---------------- scratch (static device allocations; no cudaMalloc) ----------
__device__ float g_bufA[NNODES * 256];
__device__ float g_bufB[NNODES * 256];
__device__ int   g_members[NGROUP * MAXG];
__device__ int   g_cnt[NGROUP];
__device__ float g_dis[NNODES];

// bf16 hi/lo transposed weights: [N][K] row-major (16B-aligned for cp.async)
__device__ __align__(16) __nv_bfloat16 g_w1h[256 * 128], g_w1l[256 * 128];
__device__ __align__(16) __nv_bfloat16 g_w2h[256 * 256], g_w2l[256 * 256];
__device__ __align__(16) __nv_bfloat16 g_w3h[128 * 256], g_w3l[128 * 256];

__device__ __forceinline__ uint32_t pack_bf16x2(float a, float b) {
    __nv_bfloat162 t = __floats2bfloat162_rn(a, b);
    return *reinterpret_cast<uint32_t*>(&t);
}

__device__ __forceinline__ void cp_async16(uint32_t saddr, const void* gptr) {
    asm volatile("cp.async.cg.shared.global [%0], [%1], 16;" :: "r"(saddr), "l"(gptr));
}
#define CP_COMMIT() asm volatile("cp.async.commit_group;" ::: "memory")
#define CP_WAIT0()  asm volatile("cp.async.wait_group 0;" ::: "memory")

// ---------------- 1) group build (4 elems/thread/tile) ------------------------
__global__ __launch_bounds__(256) void build_groups(const void* __restrict__ idx_raw, int n) {
    const int g    = blockIdx.x;
    const int tid  = threadIdx.x;
    const int lane = tid & 31;
    const int warp = tid >> 5;
    const int*       idx32 = (const int*)idx_raw;
    const long long* idx64 = (const long long*)idx_raw;

    __shared__ int warp_sums[8];
    __shared__ int s_base;
    __shared__ unsigned s_any[8];

    {
        bool bad = false;
        int i = tid;
        if (i < n / 2) {
            int lo = idx32[2 * i];
            int hi = idx32[2 * i + 1];
            bad = (hi != 0) || (lo < 0) || (lo >= NGROUP);
        }
        unsigned m = __ballot_sync(0xffffffffu, bad);
        if (lane == 0) s_any[warp] = m;
    }
    if (tid == 0) s_base = 0;
    __syncthreads();
    unsigned any = 0;
#pragma unroll
    for (int w = 0; w < 8; w++) any |= s_any[w];
    const int is64 = (any == 0) ? 1 : 0;
    __syncthreads();

    for (int t0 = 0; t0 < n; t0 += 1024) {
        int i0 = t0 + tid * 4;
        int v[4];
        if (!is64 && i0 + 3 < n) {
            int4 q = *reinterpret_cast<const int4*>(&idx32[i0]);
            v[0] = q.x; v[1] = q.y; v[2] = q.z; v[3] = q.w;
        } else {
#pragma unroll
            for (int j = 0; j < 4; j++) {
                int i = i0 + j;
                v[j] = (i < n) ? (is64 ? (int)idx64[i] : idx32[i]) : -1;
            }
        }
        unsigned m[4];
#pragma unroll
        for (int j = 0; j < 4; j++) m[j] = __ballot_sync(0xffffffffu, v[j] == g);
        unsigned lt = (1u << lane) - 1u;
        int lanebase = 0, wtotal = 0;
#pragma unroll
        for (int j = 0; j < 4; j++) { lanebase += __popc(m[j] & lt); wtotal += __popc(m[j]); }
        if (lane == 0) warp_sums[warp] = wtotal;
        __syncthreads();
        int woff = 0, tile_total = 0;
#pragma unroll
        for (int w = 0; w < 8; w++) {
            if (w < warp) woff += warp_sums[w];
            tile_total += warp_sums[w];
        }
        int mycnt = 0;
#pragma unroll
        for (int j = 0; j < 4; j++) {
            if (v[j] == g) {
                int pos = s_base + woff + lanebase + mycnt;
                g_members[g * MAXG + pos] = i0 + j;
                g_dis[i0 + j] = rsqrtf((float)(pos + 1));
                mycnt++;
            }
        }
        __syncthreads();
        if (tid == 0) s_base += tile_total;
        __syncthreads();
    }
    if (tid == 0) g_cnt[g] = s_base;
}

// ---------------- 2) weight prep, split into W1 and W2+W3 ---------------------
__global__ void prep_w1(const float* __restrict__ W1) {
    int e = blockIdx.x * 256 + threadIdx.x;   // 32768 elems
    const int K = 128, N = 256;
    int n = e / K, k = e - n * K;
    float v = W1[(size_t)k * N + n];
    __nv_bfloat16 h = __float2bfloat16(v);
    g_w1h[e] = h;
    g_w1l[e] = __float2bfloat16(v - __bfloat162float(h));
}

__global__ void prep_w23(const float* __restrict__ W2, const float* __restrict__ W3) {
    int e = blockIdx.x * 256 + threadIdx.x;   // 98304 elems
    const float* W;
    __nv_bfloat16 *oh, *ol;
    int K, N;
    if (e < 65536) { W = W2; oh = g_w2h; ol = g_w2l; K = 256; N = 256; }
    else           { e -= 65536; W = W3; oh = g_w3h; ol = g_w3l; K = 256; N = 128; }
    int n = e / K, k = e - n * K;
    float v = W[(size_t)k * N + n];
    __nv_bfloat16 h = __float2bfloat16(v);
    oh[e] = h;
    ol[e] = __float2bfloat16(v - __bfloat162float(h));
}

// ---------------- 3) HMMA GEMM (R12 kernel, unchanged) ------------------------
#define LDMX4(r0, r1, r2, r3, addr) \
    asm volatile("ldmatrix.sync.aligned.m8n8.x4.shared.b16 {%0,%1,%2,%3}, [%4];" \
                 : "=r"(r0), "=r"(r1), "=r"(r2), "=r"(r3) : "r"(addr))
#define MMA16816(c, a, b) \
    asm volatile("mma.sync.aligned.m16n8k16.row.col.f32.bf16.bf16.f32 " \
                 "{%0,%1,%2,%3}, {%4,%5,%6,%7}, {%8,%9}, {%0,%1,%2,%3};" \
                 : "+f"((c)[0]), "+f"((c)[1]), "+f"((c)[2]), "+f"((c)[3]) \
                 : "r"((a)[0]), "r"((a)[1]), "r"((a)[2]), "r"((a)[3]), \
                   "r"((b)[0]), "r"((b)[1]))

__global__ __launch_bounds__(256) void gemm_mma(const float* __restrict__ A,
                                                const __nv_bfloat16* __restrict__ Wh,
                                                const __nv_bfloat16* __restrict__ Wl,
                                                float* __restrict__ C,
                                                int M, int K, int N) {
    __shared__ __align__(16) __nv_bfloat16 sAh[128][40];
    __shared__ __align__(16) __nv_bfloat16 sAl[128][40];
    __shared__ __align__(16) __nv_bfloat16 sBh[128][40];
    __shared__ __align__(16) __nv_bfloat16 sBl[128][40];

    const int tid  = threadIdx.x;
    const int wid  = tid >> 5;
    const int lane = tid & 31;
    const int bm   = blockIdx.x * 128;
    const int bn   = blockIdx.y * 128;
    const int wm   = (wid & 1) * 64;
    const int wn   = (wid >> 1) * 32;

    const __nv_bfloat16* WhB = Wh + (size_t)bn * K;
    const __nv_bfloat16* WlB = Wl + (size_t)bn * K;

    float acc[4][4][4];
#pragma unroll
    for (int i = 0; i < 4; i++)
#pragma unroll
        for (int j = 0; j < 4; j++)
#pragma unroll
            for (int q = 0; q < 4; q++) acc[i][j][q] = 0.0f;

    const int lrow = lane & 15;
    const int lcol = (lane >> 4) << 3;

    const int brow0 = tid >> 2,            bseg0 = (tid & 3) << 3;
    const int brow1 = (tid + 256) >> 2,    bseg1 = ((tid + 256) & 3) << 3;

    for (int kc = 0; kc < K; kc += 32) {
        __syncthreads();
        cp_async16((uint32_t)__cvta_generic_to_shared(&sBh[brow0][bseg0]), &WhB[(size_t)brow0 * K + kc + bseg0]);
        cp_async16((uint32_t)__cvta_generic_to_shared(&sBh[brow1][bseg1]), &WhB[(size_t)brow1 * K + kc + bseg1]);
        cp_async16((uint32_t)__cvta_generic_to_shared(&sBl[brow0][bseg0]), &WlB[(size_t)brow0 * K + kc + bseg0]);
        cp_async16((uint32_t)__cvta_generic_to_shared(&sBl[brow1][bseg1]), &WlB[(size_t)brow1 * K + kc + bseg1]);
        CP_COMMIT();
#pragma unroll
        for (int e = tid; e < 1024; e += 256) {
            int row = e >> 3, seg = (e & 7) << 2;
            float4 a = make_float4(0.f, 0.f, 0.f, 0.f);
            int gr = bm + row;
            if (gr < M) a = *reinterpret_cast<const float4*>(&A[(size_t)gr * K + kc + seg]);
            __nv_bfloat16 h0 = __float2bfloat16(a.x), h1 = __float2bfloat16(a.y);
            __nv_bfloat16 h2 = __float2bfloat16(a.z), h3 = __float2bfloat16(a.w);
            uint2 uh, ul;
            uh.x = ((uint32_t)*(uint16_t*)&h1 << 16) | *(uint16_t*)&h0;
            uh.y = ((uint32_t)*(uint16_t*)&h3 << 16) | *(uint16_t*)&h2;
            ul.x = pack_bf16x2(a.x - __bfloat162float(h0), a.y - __bfloat162float(h1));
            ul.y = pack_bf16x2(a.z - __bfloat162float(h2), a.w - __bfloat162float(h3));
            *reinterpret_cast<uint2*>(&sAh[row][seg]) = uh;
            *reinterpret_cast<uint2*>(&sAl[row][seg]) = ul;
        }
        CP_WAIT0();
        __syncthreads();

#pragma unroll
        for (int ks = 0; ks < 2; ks++) {
            const int k0 = ks * 16;
            uint32_t ah[4][4], al[4][4], bh[4][2], bl[4][2];
#pragma unroll
            for (int mi = 0; mi < 4; mi++) {
                uint32_t adrh = (uint32_t)__cvta_generic_to_shared(&sAh[wm + mi * 16 + lrow][k0 + lcol]);
                uint32_t adrl = (uint32_t)__cvta_generic_to_shared(&sAl[wm + mi * 16 + lrow][k0 + lcol]);
                LDMX4(ah[mi][0], ah[mi][1], ah[mi][2], ah[mi][3], adrh);
                LDMX4(al[mi][0], al[mi][1], al[mi][2], al[mi][3], adrl);
            }
#pragma unroll
            for (int nj = 0; nj < 2; nj++) {
                uint32_t r0, r1, r2, r3;
                uint32_t adrh = (uint32_t)__cvta_generic_to_shared(&sBh[wn + nj * 16 + lrow][k0 + lcol]);
                LDMX4(r0, r1, r2, r3, adrh);
                bh[nj * 2 + 0][0] = r0; bh[nj * 2 + 0][1] = r2;
                bh[nj * 2 + 1][0] = r1; bh[nj * 2 + 1][1] = r3;
                uint32_t adrl = (uint32_t)__cvta_generic_to_shared(&sBl[wn + nj * 16 + lrow][k0 + lcol]);
                LDMX4(r0, r1, r2, r3, adrl);
                bl[nj * 2 + 0][0] = r0; bl[nj * 2 + 0][1] = r2;
                bl[nj * 2 + 1][0] = r1; bl[nj * 2 + 1][1] = r3;
            }
#pragma unroll
            for (int mi = 0; mi < 4; mi++)
#pragma unroll
                for (int nt = 0; nt < 4; nt++) {
                    MMA16816(acc[mi][nt], ah[mi], bh[nt]);
                    MMA16816(acc[mi][nt], al[mi], bh[nt]);
                    MMA16816(acc[mi][nt], ah[mi], bl[nt]);
                }
        }
    }

    const int trow = lane >> 2;
    const int tcol = (lane & 3) * 2;
#pragma unroll
    for (int mi = 0; mi < 4; mi++) {
        int r0 = bm + wm + mi * 16 + trow;
#pragma unroll
        for (int nt = 0; nt < 4; nt++) {
            int c0 = bn + wn + nt * 8 + tcol;
            if (r0 < M)
                *reinterpret_cast<float2*>(&C[(size_t)r0 * N + c0]) =
                    make_float2(acc[mi][nt][0], acc[mi][nt][1]);
            if (r0 + 8 < M)
                *reinterpret_cast<float2*>(&C[(size_t)(r0 + 8) * N + c0]) =
                    make_float2(acc[mi][nt][2], acc[mi][nt][3]);
        }
    }
}

// ---------------- 4) per-group prefix scan + bias + relu (quad-batched) -------
__global__ __launch_bounds__(128) void scan_relu(const float* __restrict__ H,
                                                 const float* __restrict__ bias,
                                                 float* __restrict__ out, int D) {
    __shared__ int   s_mem[MAXG];
    __shared__ float s_dis[MAXG];
    const int g = blockIdx.x;
    const int c = g_cnt[g];
    for (int m = threadIdx.x; m < c; m += 128) {
        int i = g_members[g * MAXG + m];
        s_mem[m] = i;
        s_dis[m] = g_dis[i];
    }
    __syncthreads();
    const int f = blockIdx.y * 128 + threadIdx.x;
    float acc = 0.0f;
    const float bf = bias[f];
    int m = 0;
    for (; m + 4 <= c; m += 4) {
        int   id0 = s_mem[m + 0], id1 = s_mem[m + 1], id2 = s_mem[m + 2], id3 = s_mem[m + 3];
        float d0 = s_dis[m + 0], d1 = s_dis[m + 1], d2 = s_dis[m + 2], d3 = s_dis[m + 3];
        float v0 = __ldg(&H[(size_t)id0 * D + f]);
        float v1 = __ldg(&H[(size_t)id1 * D + f]);
        float v2 = __ldg(&H[(size_t)id2 * D + f]);
        float v3 = __ldg(&H[(size_t)id3 * D + f]);
        acc = fmaf(d0, v0, acc);
        out[(size_t)id0 * D + f] = fmaxf(fmaf(d0, acc, bf), 0.0f);
        acc = fmaf(d1, v1, acc);
        out[(size_t)id1 * D + f] = fmaxf(fmaf(d1, acc, bf), 0.0f);
        acc = fmaf(d2, v2, acc);
        out[(size_t)id2 * D + f] = fmaxf(fmaf(d2, acc, bf), 0.0f);
        acc = fmaf(d3, v3, acc);
        out[(size_t)id3 * D + f] = fmaxf(fmaf(d3, acc, bf), 0.0f);
    }
    for (; m < c; m++) {
        int   i = s_mem[m];
        float d = s_dis[m];
        acc = fmaf(d, __ldg(&H[(size_t)i * D + f]), acc);
        out[(size_t)i * D + f] = fmaxf(fmaf(d, acc, bf), 0.0f);
    }
}

// ---------------- 5) LayerNorm over last dim (128) ----------------------------
__global__ __launch_bounds__(256) void layernorm128(const float* __restrict__ h,
                                                    const float* __restrict__ gamma,
                                                    const float* __restrict__ beta,
                                                    float* __restrict__ out, int n) {
    int row = blockIdx.x * (blockDim.x >> 5) + (threadIdx.x >> 5);
    if (row >= n) return;
    int lane = threadIdx.x & 31;
    float4 v = reinterpret_cast<const float4*>(h + (size_t)row * 128)[lane];
    float s = v.x + v.y + v.z + v.w;
#pragma unroll
    for (int o = 16; o; o >>= 1) s += __shfl_xor_sync(0xffffffffu, s, o);
    float mu = s * (1.0f / 128.0f);
    float dx = v.x - mu, dy = v.y - mu, dz = v.z - mu, dw = v.w - mu;
    float q = dx * dx + dy * dy + dz * dz + dw * dw;
#pragma unroll
    for (int o = 16; o; o >>= 1) q += __shfl_xor_sync(0xffffffffu, q, o);
    float inv = rsqrtf(q * (1.0f / 128.0f) + 1e-5f);
    float4 ga = reinterpret_cast<const float4*>(gamma)[lane];
    float4 be = reinterpret_cast<const float4*>(beta)[lane];
    float4 o4;
    o4.x = fmaf(dx * inv, ga.x, be.x);
    o4.y = fmaf(dy * inv, ga.y, be.y);
    o4.z = fmaf(dz * inv, ga.z, be.z);
    o4.w = fmaf(dw * inv, ga.w, be.w);
    reinterpret_cast<float4*>(out + (size_t)row * 128)[lane] = o4;
}

// ---------------- launch ------------------------------------------------------
extern "C" void kernel_launch(void* const* d_in, const int* in_sizes, int n_in,
                              void* d_out, int out_size) {
    const float* x     = (const float*)d_in[0];
    const void*  idx   = d_in[1];
    const float* W1    = (const float*)d_in[2];
    const float* b1    = (const float*)d_in[3];
    const float* W2    = (const float*)d_in[4];
    const float* b2    = (const float*)d_in[5];
    const float* W3    = (const float*)d_in[6];
    const float* b3    = (const float*)d_in[7];
    const float* gamma = (const float*)d_in[8];
    const float* beta  = (const float*)d_in[9];
    float* out = (float*)d_out;

    float *bufA = nullptr, *bufB = nullptr;
    __nv_bfloat16 *w1h, *w1l, *w2h, *w2l, *w3h, *w3l;
    cudaGetSymbolAddress((void**)&bufA, g_bufA);
    cudaGetSymbolAddress((void**)&bufB, g_bufB);
    cudaGetSymbolAddress((void**)&w1h, g_w1h);
    cudaGetSymbolAddress((void**)&w1l, g_w1l);
    cudaGetSymbolAddress((void**)&w2h, g_w2h);
    cudaGetSymbolAddress((void**)&w2l, g_w2l);
    cudaGetSymbolAddress((void**)&w3h, g_w3h);
    cudaGetSymbolAddress((void**)&w3l, g_w3l);

    // one-time side stream + events (no device memory involved)
    static cudaStream_t s1 = nullptr;
    static cudaEvent_t  ev0 = nullptr, ev1 = nullptr;
    if (s1 == nullptr) {
        cudaStreamCreateWithFlags(&s1, cudaStreamNonBlocking);
        cudaEventCreateWithFlags(&ev0, cudaEventDisableTiming);
        cudaEventCreateWithFlags(&ev1, cudaEventDisableTiming);
    }

    const int n = NNODES;
    const int mtiles = (n + 127) / 128;  // 157

    // fork: build_groups + prep_w23 run concurrently with prep_w1 + gemm1
    cudaEventRecord(ev0, 0);
    cudaStreamWaitEvent(s1, ev0, 0);
    build_groups<<<NGROUP, 256, 0, s1>>>(idx, n);
    prep_w23<<<(65536 + 32768) / 256, 256, 0, s1>>>(W2, W3);
    cudaEventRecord(ev1, s1);

    prep_w1<<<32768 / 256, 256>>>(W1);
    // layer 1: x[20000,128] @ W1 -> bufA[20000,256]  (independent of fork work)
    gemm_mma<<<dim3(mtiles, 2), 256>>>(x, w1h, w1l, bufA, n, 128, 256);

    // join: scan1 needs build_groups output; gemm2 needs W2
    cudaStreamWaitEvent(0, ev1, 0);

    scan_relu<<<dim3(NGROUP, 2), 128>>>(bufA, b1, bufB, 256);
    // layer 2: [20000,256] @ W2 -> bufA
    gemm_mma<<<dim3(mtiles, 2), 256>>>(bufB, w2h, w2l, bufA, n, 256, 256);
    scan_relu<<<dim3(NGROUP, 2), 128>>>(bufA, b2, bufB, 256);
    // layer 3: [20000,256] @ W3 -> bufA (N=128)
    gemm_mma<<<dim3(mtiles, 1), 256>>>(bufB, w3h, w3l, bufA, n, 256, 128);
    scan_relu<<<dim3(NGROUP, 1), 128>>>(bufA, b3, bufB, 128);

    layernorm128<<<(n + 7) / 8, 256>>>(bufB, gamma, beta, out, n);
}